// round 2
// baseline (speedup 1.0000x reference)
#include <cuda_runtime.h>
#include <cuda_bf16.h>
#include <cstdint>

// ---------------- Problem sizes ----------------
#define TOKENS 4096
#define IN_F   8192
#define OUT_F  8192

#define KCHUNK   64                     // int8 elems of K per pipeline stage
#define KITERS   (IN_F / KCHUNK)        // 128
#define MTILES   (TOKENS / 128)         // 32
#define NTILES   (OUT_F / 128)          // 64

// SMEM staging: rows padded 64 -> 80 bytes (20-bank group stride => conflict-free frags)
#define ROW_PAD     80
#define A_STAGE     (128 * ROW_PAD)     // 10240
#define B_STAGE     (128 * ROW_PAD)     // 10240
#define STAGE_BYTES (A_STAGE + B_STAGE) // 20480
#define NSTAGES     4
#define GEMM_SMEM   (NSTAGES * STAGE_BYTES)  // 81920

// ---------------- Scratch (device globals; no allocation) ----------------
// Tiled layouts: [tile_row_block][kt][128 rows][64 bytes] -> each stage load is one
// contiguous 8 KB block per operand.
__device__ uint8_t g_A8[(size_t)TOKENS * IN_F];  // 32 MB
__device__ uint8_t g_B8[(size_t)OUT_F  * IN_F];  // 64 MB
__device__ float   g_s[TOKENS];                  // per-row activation scale s

// ---------------- PTX helpers ----------------
__device__ __forceinline__ uint32_t smem_to_u32(const void* smem_ptr) {
    uint32_t addr;
    asm("{ .reg .u64 tmp; cvta.to.shared.u64 tmp, %1; cvt.u32.u64 %0, tmp; }"
        : "=r"(addr) : "l"(smem_ptr));
    return addr;
}

#define CP_ASYNC16(dst, src) \
    asm volatile("cp.async.cg.shared.global [%0], [%1], 16;" \
        :: "r"((uint32_t)(dst)), "l"(src) : "memory")

#define CP_COMMIT() asm volatile("cp.async.commit_group;" ::: "memory")
#define CP_WAIT2()  asm volatile("cp.async.wait_group 2;" ::: "memory")

#define MMA_S8(c, a, b0, b1) \
    asm volatile( \
        "mma.sync.aligned.m16n8k32.row.col.s32.s8.s8.s32 " \
        "{%0,%1,%2,%3}, {%4,%5,%6,%7}, {%8,%9}, {%0,%1,%2,%3};" \
        : "+r"((c)[0]), "+r"((c)[1]), "+r"((c)[2]), "+r"((c)[3]) \
        : "r"((a)[0]), "r"((a)[1]), "r"((a)[2]), "r"((a)[3]), \
          "r"(b0), "r"(b1))

// ---------------- Kernel 1: per-row quantize x -> int8 (tiled) + scale ----------------
__global__ void __launch_bounds__(256, 1) quant_kernel(const float* __restrict__ x) {
    int t = blockIdx.x;
    int tid = threadIdx.x;
    const float4* xr = reinterpret_cast<const float4*>(x + (size_t)t * IN_F) + tid * 8;

    float vv[32];
    float m = 0.0f;
#pragma unroll
    for (int j = 0; j < 8; j++) {
        float4 v4 = xr[j];
        vv[4 * j + 0] = v4.x; vv[4 * j + 1] = v4.y;
        vv[4 * j + 2] = v4.z; vv[4 * j + 3] = v4.w;
        m = fmaxf(m, fmaxf(fmaxf(fabsf(v4.x), fabsf(v4.y)), fmaxf(fabsf(v4.z), fabsf(v4.w))));
    }
#pragma unroll
    for (int o = 16; o > 0; o >>= 1)
        m = fmaxf(m, __shfl_xor_sync(0xFFFFFFFFu, m, o));

    __shared__ float wm[8];
    __shared__ float sh_s;
    if ((tid & 31) == 0) wm[tid >> 5] = m;
    __syncthreads();
    if (tid == 0) {
        float mm = wm[0];
#pragma unroll
        for (int j = 1; j < 8; j++) mm = fmaxf(mm, wm[j]);
        float s = 127.0f / fmaxf(mm, 1e-5f);
        g_s[t] = s;
        sh_s = s;
    }
    __syncthreads();
    float s = sh_s;

    int k0  = tid * 32;
    int kt  = k0 >> 6;
    int c0  = k0 & 63;               // 0 or 32
    int m_t = t >> 7;
    int r   = t & 127;
    uint8_t* dst = g_A8 + ((size_t)(m_t * KITERS + kt) << 13) + r * 64 + c0;

    uint32_t pk[8];
#pragma unroll
    for (int p = 0; p < 8; p++) {
        int q0 = __float2int_rn(vv[4 * p + 0] * s);
        int q1 = __float2int_rn(vv[4 * p + 1] * s);
        int q2 = __float2int_rn(vv[4 * p + 2] * s);
        int q3 = __float2int_rn(vv[4 * p + 3] * s);
        q0 = max(-128, min(127, q0)); q1 = max(-128, min(127, q1));
        q2 = max(-128, min(127, q2)); q3 = max(-128, min(127, q3));
        pk[p] = (uint32_t)(q0 & 0xFF) | ((uint32_t)(q1 & 0xFF) << 8) |
                ((uint32_t)(q2 & 0xFF) << 16) | ((uint32_t)(q3 & 0xFF) << 24);
    }
    uint4* d4 = reinterpret_cast<uint4*>(dst);
    d4[0] = make_uint4(pk[0], pk[1], pk[2], pk[3]);
    d4[1] = make_uint4(pk[4], pk[5], pk[6], pk[7]);
}

// ---------------- Kernel 2: weight int32{0,1} -> int8 (tiled) ----------------
__global__ void __launch_bounds__(256, 1) wconv_kernel(const int* __restrict__ w) {
    int n = blockIdx.x;
    int tid = threadIdx.x;
    int k0 = tid * 32;
    const int4* wr = reinterpret_cast<const int4*>(w + (size_t)n * IN_F + k0);

    int kt  = k0 >> 6;
    int c0  = k0 & 63;
    int n_t = n >> 7;
    int r   = n & 127;
    uint8_t* dst = g_B8 + ((size_t)(n_t * KITERS + kt) << 13) + r * 64 + c0;

    uint32_t pk[8];
#pragma unroll
    for (int p = 0; p < 8; p++) {
        int4 q = wr[p];
        pk[p] = (uint32_t)(q.x & 0xFF) | ((uint32_t)(q.y & 0xFF) << 8) |
                ((uint32_t)(q.z & 0xFF) << 16) | ((uint32_t)(q.w & 0xFF) << 24);
    }
    uint4* d4 = reinterpret_cast<uint4*>(dst);
    d4[0] = make_uint4(pk[0], pk[1], pk[2], pk[3]);
    d4[1] = make_uint4(pk[4], pk[5], pk[6], pk[7]);
}

// ---------------- Kernel 3: pipelined int8 IMMA GEMM, fused dequant epilogue ----------------
// CTA tile 128(M) x 128(N). 8 warps: warp_m = wid&3 (32 rows), warp_n = wid>>2 (64 cols).
// Warp tile 32x64 = 2 m-blocks(16) x 8 n-blocks(8), K-step 32 (two per 64-elem stage).
__global__ void __launch_bounds__(256) gemm_kernel(
    const float* __restrict__ wscale,
    const float* __restrict__ bias,
    float* __restrict__ out
) {
    extern __shared__ char smem[];
    uint32_t sb = smem_to_u32(smem);
    int tid  = threadIdx.x;
    int wid  = tid >> 5;
    int lane = tid & 31;
    int wm = wid & 3;
    int wn = wid >> 2;
    int g   = lane >> 2;   // group id 0..7
    int tig = lane & 3;    // thread in group

    int n_t = blockIdx.x;  // 0..63
    int m_t = blockIdx.y;  // 0..31

    const uint8_t* Ag = g_A8 + ((size_t)(m_t * KITERS) << 13);
    const uint8_t* Bg = g_B8 + ((size_t)(n_t * KITERS) << 13);

    // per-thread cp.async assignments: 2 x 16B per operand per stage
    int idxs[2] = { tid, tid + 256 };

    int acc[2][8][4];
#pragma unroll
    for (int mb = 0; mb < 2; mb++)
#pragma unroll
        for (int nb = 0; nb < 8; nb++)
#pragma unroll
            for (int i = 0; i < 4; i++) acc[mb][nb][i] = 0;

    // ---- prologue: stages 0..2 ----
#pragma unroll
    for (int p = 0; p < NSTAGES - 1; p++) {
        uint32_t dstA = sb + p * STAGE_BYTES;
        uint32_t dstB = dstA + A_STAGE;
        const uint8_t* srcA = Ag + ((size_t)p << 13);
        const uint8_t* srcB = Bg + ((size_t)p << 13);
#pragma unroll
        for (int j = 0; j < 2; j++) {
            int idx = idxs[j];
            int r = idx >> 2, c = idx & 3;
            CP_ASYNC16(dstA + r * ROW_PAD + c * 16, srcA + idx * 16);
            CP_ASYNC16(dstB + r * ROW_PAD + c * 16, srcB + idx * 16);
        }
        CP_COMMIT();
    }

    // ---- mainloop ----
    for (int kt = 0; kt < KITERS; kt++) {
        CP_WAIT2();
        __syncthreads();

        // issue loads for stage kt+3 (overwrites stage consumed at iter kt-1)
        int kn = kt + NSTAGES - 1;
        if (kn < KITERS) {
            int sn = kn & (NSTAGES - 1);
            uint32_t dstA = sb + sn * STAGE_BYTES;
            uint32_t dstB = dstA + A_STAGE;
            const uint8_t* srcA = Ag + ((size_t)kn << 13);
            const uint8_t* srcB = Bg + ((size_t)kn << 13);
#pragma unroll
            for (int j = 0; j < 2; j++) {
                int idx = idxs[j];
                int r = idx >> 2, c = idx & 3;
                CP_ASYNC16(dstA + r * ROW_PAD + c * 16, srcA + idx * 16);
                CP_ASYNC16(dstB + r * ROW_PAD + c * 16, srcB + idx * 16);
            }
        }
        CP_COMMIT();

        // compute stage kt
        int s = kt & (NSTAGES - 1);
        const char* As = smem + s * STAGE_BYTES;
        const char* Bs = As + A_STAGE;

#pragma unroll
        for (int ks = 0; ks < 2; ks++) {
            uint32_t a[2][4];
#pragma unroll
            for (int mb = 0; mb < 2; mb++) {
                const char* ab = As + (wm * 32 + mb * 16 + g) * ROW_PAD + ks * 32 + tig * 4;
                a[mb][0] = *reinterpret_cast<const uint32_t*>(ab);
                a[mb][1] = *reinterpret_cast<const uint32_t*>(ab + 8 * ROW_PAD);
                a[mb][2] = *reinterpret_cast<const uint32_t*>(ab + 16);
                a[mb][3] = *reinterpret_cast<const uint32_t*>(ab + 8 * ROW_PAD + 16);
            }
#pragma unroll
            for (int nb = 0; nb < 8; nb++) {
                const char* bb = Bs + (wn * 64 + nb * 8 + g) * ROW_PAD + ks * 32 + tig * 4;
                uint32_t b0 = *reinterpret_cast<const uint32_t*>(bb);
                uint32_t b1 = *reinterpret_cast<const uint32_t*>(bb + 16);
                MMA_S8(acc[0][nb], a[0], b0, b1);
                MMA_S8(acc[1][nb], a[1], b0, b1);
            }
        }
    }

    // ---- epilogue: dequant + bias, direct to gmem ----
    float wsc = wscale[0];
#pragma unroll
    for (int mb = 0; mb < 2; mb++) {
        int r_a = m_t * 128 + wm * 32 + mb * 16 + g;
        int r_b = r_a + 8;
        float sca = 1.0f / (g_s[r_a] * wsc);
        float scb = 1.0f / (g_s[r_b] * wsc);
        float* outa = out + (size_t)r_a * OUT_F;
        float* outb = out + (size_t)r_b * OUT_F;
#pragma unroll
        for (int nb = 0; nb < 8; nb++) {
            int col = n_t * 128 + wn * 64 + nb * 8 + tig * 2;
            float2 bi = *reinterpret_cast<const float2*>(bias + col);
            float2 o;
            o.x = (float)acc[mb][nb][0] * sca + bi.x;
            o.y = (float)acc[mb][nb][1] * sca + bi.y;
            *reinterpret_cast<float2*>(outa + col) = o;
            o.x = (float)acc[mb][nb][2] * scb + bi.x;
            o.y = (float)acc[mb][nb][3] * scb + bi.y;
            *reinterpret_cast<float2*>(outb + col) = o;
        }
    }
}

// ---------------- Launch ----------------
extern "C" void kernel_launch(void* const* d_in, const int* in_sizes, int n_in,
                              void* d_out, int out_size) {
    const float* x      = (const float*)d_in[0];
    const int*   weight = (const int*)d_in[1];
    const float* wscale = (const float*)d_in[2];
    const float* bias   = (const float*)d_in[3];
    float*       out    = (float*)d_out;

    quant_kernel<<<TOKENS, 256>>>(x);
    wconv_kernel<<<OUT_F, 256>>>(weight);

    cudaFuncSetAttribute(gemm_kernel, cudaFuncAttributeMaxDynamicSharedMemorySize, GEMM_SMEM);
    gemm_kernel<<<dim3(NTILES, MTILES), 256, GEMM_SMEM>>>(wscale, bias, out);
}

// round 3
// speedup vs baseline: 1.3892x; 1.3892x over previous
#include <cuda_runtime.h>
#include <cuda_bf16.h>
#include <cstdint>

// ---------------- Problem sizes ----------------
#define TOKENS 4096
#define IN_F   8192
#define OUT_F  8192

#define TOK_SPLIT 2048                  // tokens [0,2048) -> int8 path, [2048,4096) -> bf16 path

#define KCHUNK   64                     // K elems per pipeline stage (both paths)
#define KITERS   (IN_F / KCHUNK)        // 128
#define NTILES   (OUT_F / 128)          // 64
#define MT_I8    (TOK_SPLIT / 128)      // 16
#define MT_BF    ((TOKENS - TOK_SPLIT) / 128) // 16

// ---- int8 GEMM staging (as R2) ----
#define ROW_PAD     80
#define A_STAGE     (128 * ROW_PAD)
#define B_STAGE     (128 * ROW_PAD)
#define STAGE_BYTES (A_STAGE + B_STAGE)
#define NSTAGES     4
#define GEMM_SMEM   (NSTAGES * STAGE_BYTES)      // 81920

// ---- bf16 GEMM staging ----
#define ROWB        144                 // 128B data + 16B pad (bank stride 36 -> conflict-free)
#define A_STAGE_B   (128 * ROWB)        // 18432
#define STAGE_B     (2 * A_STAGE_B)     // 36864
#define NSTAGES_B   3
#define GEMM_SMEM_B (NSTAGES_B * STAGE_B)        // 110592

// ---------------- Scratch ----------------
__device__ uint8_t        g_A8[(size_t)TOK_SPLIT * IN_F];            // 16 MB
__device__ uint8_t        g_B8[(size_t)OUT_F * IN_F];                // 64 MB
__device__ __nv_bfloat16  g_Ab[(size_t)(TOKENS - TOK_SPLIT) * IN_F]; // 32 MB
__device__ __nv_bfloat16  g_Bb[(size_t)OUT_F * IN_F];                // 128 MB
__device__ float          g_s[TOKENS];

// ---------------- PTX helpers ----------------
__device__ __forceinline__ uint32_t smem_to_u32(const void* smem_ptr) {
    uint32_t addr;
    asm("{ .reg .u64 tmp; cvta.to.shared.u64 tmp, %1; cvt.u32.u64 %0, tmp; }"
        : "=r"(addr) : "l"(smem_ptr));
    return addr;
}

#define CP_ASYNC16(dst, src) \
    asm volatile("cp.async.cg.shared.global [%0], [%1], 16;" \
        :: "r"((uint32_t)(dst)), "l"(src) : "memory")
#define CP_COMMIT() asm volatile("cp.async.commit_group;" ::: "memory")
#define CP_WAIT2()  asm volatile("cp.async.wait_group 2;" ::: "memory")
#define CP_WAIT1()  asm volatile("cp.async.wait_group 1;" ::: "memory")

#define MMA_S8(c, a, b0, b1) \
    asm volatile( \
        "mma.sync.aligned.m16n8k32.row.col.s32.s8.s8.s32 " \
        "{%0,%1,%2,%3}, {%4,%5,%6,%7}, {%8,%9}, {%0,%1,%2,%3};" \
        : "+r"((c)[0]), "+r"((c)[1]), "+r"((c)[2]), "+r"((c)[3]) \
        : "r"((a)[0]), "r"((a)[1]), "r"((a)[2]), "r"((a)[3]), \
          "r"(b0), "r"(b1))

#define MMA_BF16(c, a, b0, b1) \
    asm volatile( \
        "mma.sync.aligned.m16n8k16.row.col.f32.bf16.bf16.f32 " \
        "{%0,%1,%2,%3}, {%4,%5,%6,%7}, {%8,%9}, {%0,%1,%2,%3};" \
        : "+f"((c)[0]), "+f"((c)[1]), "+f"((c)[2]), "+f"((c)[3]) \
        : "r"((a)[0]), "r"((a)[1]), "r"((a)[2]), "r"((a)[3]), \
          "r"(b0), "r"(b1))

// ---------------- Kernel 1: quantize x; lower half -> int8 tiles, upper -> bf16 tiles ----------------
__global__ void __launch_bounds__(256, 1) prep_x_kernel(const float* __restrict__ x) {
    int t = blockIdx.x;
    int tid = threadIdx.x;
    const float4* xr = reinterpret_cast<const float4*>(x + (size_t)t * IN_F) + tid * 8;

    float vv[32];
    float m = 0.0f;
#pragma unroll
    for (int j = 0; j < 8; j++) {
        float4 v4 = xr[j];
        vv[4 * j + 0] = v4.x; vv[4 * j + 1] = v4.y;
        vv[4 * j + 2] = v4.z; vv[4 * j + 3] = v4.w;
        m = fmaxf(m, fmaxf(fmaxf(fabsf(v4.x), fabsf(v4.y)), fmaxf(fabsf(v4.z), fabsf(v4.w))));
    }
#pragma unroll
    for (int o = 16; o > 0; o >>= 1)
        m = fmaxf(m, __shfl_xor_sync(0xFFFFFFFFu, m, o));

    __shared__ float wm[8];
    __shared__ float sh_s;
    if ((tid & 31) == 0) wm[tid >> 5] = m;
    __syncthreads();
    if (tid == 0) {
        float mm = wm[0];
#pragma unroll
        for (int j = 1; j < 8; j++) mm = fmaxf(mm, wm[j]);
        float s = 127.0f / fmaxf(mm, 1e-5f);
        g_s[t] = s;
        sh_s = s;
    }
    __syncthreads();
    float s = sh_s;

    int k0 = tid * 32;
    int kt = k0 >> 6;
    int c0 = k0 & 63;
    int r  = t & 127;

    float q[32];
#pragma unroll
    for (int p = 0; p < 32; p++)
        q[p] = fminf(fmaxf(rintf(vv[p] * s), -128.0f), 127.0f);

    if (t < TOK_SPLIT) {
        int m_t = t >> 7;
        uint8_t* dst = g_A8 + ((size_t)(m_t * KITERS + kt) << 13) + r * 64 + c0;
        uint32_t pk[8];
#pragma unroll
        for (int p = 0; p < 8; p++) {
            int q0 = (int)q[4 * p + 0], q1 = (int)q[4 * p + 1];
            int q2 = (int)q[4 * p + 2], q3 = (int)q[4 * p + 3];
            pk[p] = (uint32_t)(q0 & 0xFF) | ((uint32_t)(q1 & 0xFF) << 8) |
                    ((uint32_t)(q2 & 0xFF) << 16) | ((uint32_t)(q3 & 0xFF) << 24);
        }
        uint4* d4 = reinterpret_cast<uint4*>(dst);
        d4[0] = make_uint4(pk[0], pk[1], pk[2], pk[3]);
        d4[1] = make_uint4(pk[4], pk[5], pk[6], pk[7]);
    } else {
        int m_t = (t - TOK_SPLIT) >> 7;
        char* dst = reinterpret_cast<char*>(g_Ab) +
                    ((size_t)(m_t * KITERS + kt) << 14) + r * 128 + c0 * 2;
        uint32_t pk[16];
#pragma unroll
        for (int p = 0; p < 16; p++) {
            __nv_bfloat162 h = __floats2bfloat162_rn(q[2 * p], q[2 * p + 1]);
            pk[p] = *reinterpret_cast<uint32_t*>(&h);
        }
        uint4* d4 = reinterpret_cast<uint4*>(dst);
#pragma unroll
        for (int j = 0; j < 4; j++)
            d4[j] = make_uint4(pk[4 * j], pk[4 * j + 1], pk[4 * j + 2], pk[4 * j + 3]);
    }
}

// ---------------- Kernel 2: weights -> int8 tiles + bf16 tiles ----------------
__global__ void __launch_bounds__(256, 1) prep_w_kernel(const int* __restrict__ w) {
    int n = blockIdx.x;
    int tid = threadIdx.x;
    int k0 = tid * 32;
    const int4* wr = reinterpret_cast<const int4*>(w + (size_t)n * IN_F + k0);

    int kt  = k0 >> 6;
    int c0  = k0 & 63;
    int n_t = n >> 7;
    int r   = n & 127;

    int vals[32];
#pragma unroll
    for (int p = 0; p < 8; p++) {
        int4 qq = wr[p];
        vals[4 * p + 0] = qq.x; vals[4 * p + 1] = qq.y;
        vals[4 * p + 2] = qq.z; vals[4 * p + 3] = qq.w;
    }

    {   // int8 tiled
        uint8_t* dst = g_B8 + ((size_t)(n_t * KITERS + kt) << 13) + r * 64 + c0;
        uint32_t pk[8];
#pragma unroll
        for (int p = 0; p < 8; p++)
            pk[p] = (uint32_t)(vals[4*p] & 0xFF) | ((uint32_t)(vals[4*p+1] & 0xFF) << 8) |
                    ((uint32_t)(vals[4*p+2] & 0xFF) << 16) | ((uint32_t)(vals[4*p+3] & 0xFF) << 24);
        uint4* d4 = reinterpret_cast<uint4*>(dst);
        d4[0] = make_uint4(pk[0], pk[1], pk[2], pk[3]);
        d4[1] = make_uint4(pk[4], pk[5], pk[6], pk[7]);
    }
    {   // bf16 tiled
        char* dst = reinterpret_cast<char*>(g_Bb) +
                    ((size_t)(n_t * KITERS + kt) << 14) + r * 128 + c0 * 2;
        uint32_t pk[16];
#pragma unroll
        for (int p = 0; p < 16; p++) {
            __nv_bfloat162 h = __floats2bfloat162_rn((float)vals[2*p], (float)vals[2*p+1]);
            pk[p] = *reinterpret_cast<uint32_t*>(&h);
        }
        uint4* d4 = reinterpret_cast<uint4*>(dst);
#pragma unroll
        for (int j = 0; j < 4; j++)
            d4[j] = make_uint4(pk[4*j], pk[4*j+1], pk[4*j+2], pk[4*j+3]);
    }
}

// ---------------- Kernel 3: int8 dp4a-roofline GEMM (tokens [0, 2048)) ----------------
__global__ void __launch_bounds__(256) gemm_i8_kernel(
    const float* __restrict__ wscale,
    const float* __restrict__ bias,
    float* __restrict__ out
) {
    extern __shared__ char smem[];
    uint32_t sb = smem_to_u32(smem);
    int tid = threadIdx.x, wid = tid >> 5, lane = tid & 31;
    int wm = wid & 3, wn = wid >> 2;
    int g = lane >> 2, tig = lane & 3;

    int n_t = blockIdx.x;
    int m_t = blockIdx.y;

    const uint8_t* Ag = g_A8 + ((size_t)(m_t * KITERS) << 13);
    const uint8_t* Bg = g_B8 + ((size_t)(n_t * KITERS) << 13);
    int idxs[2] = { tid, tid + 256 };

    int acc[2][8][4];
#pragma unroll
    for (int mb = 0; mb < 2; mb++)
#pragma unroll
        for (int nb = 0; nb < 8; nb++)
#pragma unroll
            for (int i = 0; i < 4; i++) acc[mb][nb][i] = 0;

#pragma unroll
    for (int p = 0; p < NSTAGES - 1; p++) {
        uint32_t dstA = sb + p * STAGE_BYTES;
        uint32_t dstB = dstA + A_STAGE;
        const uint8_t* srcA = Ag + ((size_t)p << 13);
        const uint8_t* srcB = Bg + ((size_t)p << 13);
#pragma unroll
        for (int j = 0; j < 2; j++) {
            int idx = idxs[j], r = idx >> 2, c = idx & 3;
            CP_ASYNC16(dstA + r * ROW_PAD + c * 16, srcA + idx * 16);
            CP_ASYNC16(dstB + r * ROW_PAD + c * 16, srcB + idx * 16);
        }
        CP_COMMIT();
    }

    for (int kt = 0; kt < KITERS; kt++) {
        CP_WAIT2();
        __syncthreads();
        int kn = kt + NSTAGES - 1;
        if (kn < KITERS) {
            int sn = kn & (NSTAGES - 1);
            uint32_t dstA = sb + sn * STAGE_BYTES;
            uint32_t dstB = dstA + A_STAGE;
            const uint8_t* srcA = Ag + ((size_t)kn << 13);
            const uint8_t* srcB = Bg + ((size_t)kn << 13);
#pragma unroll
            for (int j = 0; j < 2; j++) {
                int idx = idxs[j], r = idx >> 2, c = idx & 3;
                CP_ASYNC16(dstA + r * ROW_PAD + c * 16, srcA + idx * 16);
                CP_ASYNC16(dstB + r * ROW_PAD + c * 16, srcB + idx * 16);
            }
        }
        CP_COMMIT();

        int s = kt & (NSTAGES - 1);
        const char* As = smem + s * STAGE_BYTES;
        const char* Bs = As + A_STAGE;
#pragma unroll
        for (int ks = 0; ks < 2; ks++) {
            uint32_t a[2][4];
#pragma unroll
            for (int mb = 0; mb < 2; mb++) {
                const char* ab = As + (wm * 32 + mb * 16 + g) * ROW_PAD + ks * 32 + tig * 4;
                a[mb][0] = *reinterpret_cast<const uint32_t*>(ab);
                a[mb][1] = *reinterpret_cast<const uint32_t*>(ab + 8 * ROW_PAD);
                a[mb][2] = *reinterpret_cast<const uint32_t*>(ab + 16);
                a[mb][3] = *reinterpret_cast<const uint32_t*>(ab + 8 * ROW_PAD + 16);
            }
#pragma unroll
            for (int nb = 0; nb < 8; nb++) {
                const char* bb = Bs + (wn * 64 + nb * 8 + g) * ROW_PAD + ks * 32 + tig * 4;
                uint32_t b0 = *reinterpret_cast<const uint32_t*>(bb);
                uint32_t b1 = *reinterpret_cast<const uint32_t*>(bb + 16);
                MMA_S8(acc[0][nb], a[0], b0, b1);
                MMA_S8(acc[1][nb], a[1], b0, b1);
            }
        }
    }

    float wsc = wscale[0];
#pragma unroll
    for (int mb = 0; mb < 2; mb++) {
        int r_a = m_t * 128 + wm * 32 + mb * 16 + g;
        int r_b = r_a + 8;
        float sca = 1.0f / (g_s[r_a] * wsc);
        float scb = 1.0f / (g_s[r_b] * wsc);
        float* outa = out + (size_t)r_a * OUT_F;
        float* outb = out + (size_t)r_b * OUT_F;
#pragma unroll
        for (int nb = 0; nb < 8; nb++) {
            int col = n_t * 128 + wn * 64 + nb * 8 + tig * 2;
            float2 bi = *reinterpret_cast<const float2*>(bias + col);
            float2 o;
            o.x = (float)acc[mb][nb][0] * sca + bi.x;
            o.y = (float)acc[mb][nb][1] * sca + bi.y;
            *reinterpret_cast<float2*>(outa + col) = o;
            o.x = (float)acc[mb][nb][2] * scb + bi.x;
            o.y = (float)acc[mb][nb][3] * scb + bi.y;
            *reinterpret_cast<float2*>(outb + col) = o;
        }
    }
}

// ---------------- Kernel 4: bf16 HMMA-probe GEMM (tokens [2048, 4096)) ----------------
__global__ void __launch_bounds__(256) gemm_bf_kernel(
    const float* __restrict__ wscale,
    const float* __restrict__ bias,
    float* __restrict__ out
) {
    extern __shared__ char smem[];
    uint32_t sb = smem_to_u32(smem);
    int tid = threadIdx.x, wid = tid >> 5, lane = tid & 31;
    int wm = wid & 3, wn = wid >> 2;
    int g = lane >> 2, tig = lane & 3;

    int n_t = blockIdx.x;
    int m_t = blockIdx.y;

    const char* Ag = reinterpret_cast<const char*>(g_Ab) + ((size_t)(m_t * KITERS) << 14);
    const char* Bg = reinterpret_cast<const char*>(g_Bb) + ((size_t)(n_t * KITERS) << 14);

    float acc[2][8][4];
#pragma unroll
    for (int mb = 0; mb < 2; mb++)
#pragma unroll
        for (int nb = 0; nb < 8; nb++)
#pragma unroll
            for (int i = 0; i < 4; i++) acc[mb][nb][i] = 0.0f;

    // prologue: 2 stages; each operand stage = 16 KB = 1024 x 16B chunks, 4/thread
#pragma unroll
    for (int p = 0; p < NSTAGES_B - 1; p++) {
        uint32_t dstA = sb + p * STAGE_B;
        uint32_t dstB = dstA + A_STAGE_B;
        const char* srcA = Ag + ((size_t)p << 14);
        const char* srcB = Bg + ((size_t)p << 14);
#pragma unroll
        for (int j = 0; j < 4; j++) {
            int idx = j * 256 + tid, r = idx >> 3, c = idx & 7;
            CP_ASYNC16(dstA + r * ROWB + c * 16, srcA + idx * 16);
            CP_ASYNC16(dstB + r * ROWB + c * 16, srcB + idx * 16);
        }
        CP_COMMIT();
    }

    for (int kt = 0; kt < KITERS; kt++) {
        CP_WAIT1();
        __syncthreads();
        int kn = kt + NSTAGES_B - 1;
        if (kn < KITERS) {
            int sn = kn % NSTAGES_B;
            uint32_t dstA = sb + sn * STAGE_B;
            uint32_t dstB = dstA + A_STAGE_B;
            const char* srcA = Ag + ((size_t)kn << 14);
            const char* srcB = Bg + ((size_t)kn << 14);
#pragma unroll
            for (int j = 0; j < 4; j++) {
                int idx = j * 256 + tid, r = idx >> 3, c = idx & 7;
                CP_ASYNC16(dstA + r * ROWB + c * 16, srcA + idx * 16);
                CP_ASYNC16(dstB + r * ROWB + c * 16, srcB + idx * 16);
            }
        }
        CP_COMMIT();

        int s = kt % NSTAGES_B;
        const char* As = smem + s * STAGE_B;
        const char* Bs = As + A_STAGE_B;
#pragma unroll
        for (int ks = 0; ks < 4; ks++) {           // 4 x k16 per 64-elem chunk
            uint32_t a[2][4];
#pragma unroll
            for (int mb = 0; mb < 2; mb++) {
                const char* ab = As + (wm * 32 + mb * 16 + g) * ROWB + ks * 32 + tig * 4;
                a[mb][0] = *reinterpret_cast<const uint32_t*>(ab);
                a[mb][1] = *reinterpret_cast<const uint32_t*>(ab + 8 * ROWB);
                a[mb][2] = *reinterpret_cast<const uint32_t*>(ab + 16);
                a[mb][3] = *reinterpret_cast<const uint32_t*>(ab + 8 * ROWB + 16);
            }
#pragma unroll
            for (int nb = 0; nb < 8; nb++) {
                const char* bb = Bs + (wn * 64 + nb * 8 + g) * ROWB + ks * 32 + tig * 4;
                uint32_t b0 = *reinterpret_cast<const uint32_t*>(bb);
                uint32_t b1 = *reinterpret_cast<const uint32_t*>(bb + 16);
                MMA_BF16(acc[0][nb], a[0], b0, b1);
                MMA_BF16(acc[1][nb], a[1], b0, b1);
            }
        }
    }

    float wsc = wscale[0];
#pragma unroll
    for (int mb = 0; mb < 2; mb++) {
        int r_a = TOK_SPLIT + m_t * 128 + wm * 32 + mb * 16 + g;
        int r_b = r_a + 8;
        float sca = 1.0f / (g_s[r_a] * wsc);
        float scb = 1.0f / (g_s[r_b] * wsc);
        float* outa = out + (size_t)r_a * OUT_F;
        float* outb = out + (size_t)r_b * OUT_F;
#pragma unroll
        for (int nb = 0; nb < 8; nb++) {
            int col = n_t * 128 + wn * 64 + nb * 8 + tig * 2;
            float2 bi = *reinterpret_cast<const float2*>(bias + col);
            float2 o;
            o.x = acc[mb][nb][0] * sca + bi.x;
            o.y = acc[mb][nb][1] * sca + bi.y;
            *reinterpret_cast<float2*>(outa + col) = o;
            o.x = acc[mb][nb][2] * scb + bi.x;
            o.y = acc[mb][nb][3] * scb + bi.y;
            *reinterpret_cast<float2*>(outb + col) = o;
        }
    }
}

// ---------------- Launch ----------------
extern "C" void kernel_launch(void* const* d_in, const int* in_sizes, int n_in,
                              void* d_out, int out_size) {
    const float* x      = (const float*)d_in[0];
    const int*   weight = (const int*)d_in[1];
    const float* wscale = (const float*)d_in[2];
    const float* bias   = (const float*)d_in[3];
    float*       out    = (float*)d_out;

    prep_x_kernel<<<TOKENS, 256>>>(x);
    prep_w_kernel<<<OUT_F, 256>>>(weight);

    cudaFuncSetAttribute(gemm_i8_kernel, cudaFuncAttributeMaxDynamicSharedMemorySize, GEMM_SMEM);
    cudaFuncSetAttribute(gemm_bf_kernel, cudaFuncAttributeMaxDynamicSharedMemorySize, GEMM_SMEM_B);

    gemm_i8_kernel<<<dim3(NTILES, MT_I8), 256, GEMM_SMEM>>>(wscale, bias, out);
    gemm_bf_kernel<<<dim3(NTILES, MT_BF), 256, GEMM_SMEM_B>>>(wscale, bias, out);
}

// round 6
// speedup vs baseline: 2.5223x; 1.8157x over previous
#include <cuda_runtime.h>
#include <cuda_bf16.h>
#include <cstdint>

// ---------------- Problem sizes ----------------
#define TOKENS 4096
#define IN_F   8192
#define OUT_F  8192

#define KCHUNK   64                     // K elems per pipeline stage
#define KITERS   (IN_F / KCHUNK)        // 128
#define NTILES   (OUT_F / 128)          // 64
#define MTILES   (TOKENS / 128)         // 32

// ---- bf16 GEMM staging ----
#define ROWB        144                 // 128B data + 16B pad (bank stride 36 -> conflict-free)
#define A_STAGE_B   (128 * ROWB)        // 18432
#define STAGE_B     (2 * A_STAGE_B)     // 36864
#define NSTAGES_B   3
#define GEMM_SMEM_B (NSTAGES_B * STAGE_B)        // 110592 (2 CTAs/SM)

// ---------------- Scratch ----------------
__device__ __nv_bfloat16  g_Ab[(size_t)TOKENS * IN_F];   // 64 MB, tiled [m_t][kt][128][64]
__device__ __nv_bfloat16  g_Bb[(size_t)OUT_F  * IN_F];   // 128 MB, tiled [n_t][kt][128][64]
__device__ float          g_s[TOKENS];

// ---------------- PTX helpers ----------------
__device__ __forceinline__ uint32_t smem_to_u32(const void* smem_ptr) {
    uint32_t addr;
    asm("{ .reg .u64 tmp; cvta.to.shared.u64 tmp, %1; cvt.u32.u64 %0, tmp; }"
        : "=r"(addr) : "l"(smem_ptr));
    return addr;
}

#define CP_ASYNC16(dst, src) \
    asm volatile("cp.async.cg.shared.global [%0], [%1], 16;" \
        :: "r"((uint32_t)(dst)), "l"(src) : "memory")
#define CP_COMMIT() asm volatile("cp.async.commit_group;" ::: "memory")
#define CP_WAIT1()  asm volatile("cp.async.wait_group 1;" ::: "memory")

#define MMA_BF16(c, a, b0, b1) \
    asm volatile( \
        "mma.sync.aligned.m16n8k16.row.col.f32.bf16.bf16.f32 " \
        "{%0,%1,%2,%3}, {%4,%5,%6,%7}, {%8,%9}, {%0,%1,%2,%3};" \
        : "+f"((c)[0]), "+f"((c)[1]), "+f"((c)[2]), "+f"((c)[3]) \
        : "r"((a)[0]), "r"((a)[1]), "r"((a)[2]), "r"((a)[3]), \
          "r"(b0), "r"(b1))

#define LDMX4(r, addr) \
    asm volatile("ldmatrix.sync.aligned.m8n8.x4.shared.b16 {%0,%1,%2,%3}, [%4];" \
        : "=r"((r)[0]), "=r"((r)[1]), "=r"((r)[2]), "=r"((r)[3]) \
        : "r"((uint32_t)(addr)))

// ---------------- Kernel 1: quantize x -> bf16 tiles + scale ----------------
__global__ void __launch_bounds__(256, 1) prep_x_kernel(const float* __restrict__ x) {
    int t = blockIdx.x;
    int tid = threadIdx.x;
    const float4* xr = reinterpret_cast<const float4*>(x + (size_t)t * IN_F) + tid * 8;

    float vv[32];
    float m = 0.0f;
#pragma unroll
    for (int j = 0; j < 8; j++) {
        float4 v4 = xr[j];
        vv[4 * j + 0] = v4.x; vv[4 * j + 1] = v4.y;
        vv[4 * j + 2] = v4.z; vv[4 * j + 3] = v4.w;
        m = fmaxf(m, fmaxf(fmaxf(fabsf(v4.x), fabsf(v4.y)), fmaxf(fabsf(v4.z), fabsf(v4.w))));
    }
#pragma unroll
    for (int o = 16; o > 0; o >>= 1)
        m = fmaxf(m, __shfl_xor_sync(0xFFFFFFFFu, m, o));

    __shared__ float wm[8];
    __shared__ float sh_s;
    if ((tid & 31) == 0) wm[tid >> 5] = m;
    __syncthreads();
    if (tid == 0) {
        float mm = wm[0];
#pragma unroll
        for (int j = 1; j < 8; j++) mm = fmaxf(mm, wm[j]);
        float s = 127.0f / fmaxf(mm, 1e-5f);
        g_s[t] = s;
        sh_s = s;
    }
    __syncthreads();
    float s = sh_s;

    int k0 = tid * 32;
    int kt = k0 >> 6;
    int c0 = k0 & 63;
    int r  = t & 127;
    int m_t = t >> 7;

    char* dst = reinterpret_cast<char*>(g_Ab) +
                ((size_t)(m_t * KITERS + kt) << 14) + r * 128 + c0 * 2;
    uint32_t pk[16];
#pragma unroll
    for (int p = 0; p < 16; p++) {
        float qa = fminf(fmaxf(rintf(vv[2 * p + 0] * s), -128.0f), 127.0f);
        float qb = fminf(fmaxf(rintf(vv[2 * p + 1] * s), -128.0f), 127.0f);
        __nv_bfloat162 h = __floats2bfloat162_rn(qa, qb);
        pk[p] = *reinterpret_cast<uint32_t*>(&h);
    }
    uint4* d4 = reinterpret_cast<uint4*>(dst);
#pragma unroll
    for (int j = 0; j < 4; j++)
        d4[j] = make_uint4(pk[4 * j], pk[4 * j + 1], pk[4 * j + 2], pk[4 * j + 3]);
}

// ---------------- Kernel 2: weights int32{0,1} -> bf16 tiles ----------------
__global__ void __launch_bounds__(256, 1) prep_w_kernel(const int* __restrict__ w) {
    int n = blockIdx.x;
    int tid = threadIdx.x;
    int k0 = tid * 32;
    const int4* wr = reinterpret_cast<const int4*>(w + (size_t)n * IN_F + k0);

    int kt  = k0 >> 6;
    int c0  = k0 & 63;
    int n_t = n >> 7;
    int r   = n & 127;

    char* dst = reinterpret_cast<char*>(g_Bb) +
                ((size_t)(n_t * KITERS + kt) << 14) + r * 128 + c0 * 2;
    uint32_t pk[16];
#pragma unroll
    for (int p = 0; p < 8; p++) {
        int4 q = wr[p];
        __nv_bfloat162 h0 = __floats2bfloat162_rn((float)q.x, (float)q.y);
        __nv_bfloat162 h1 = __floats2bfloat162_rn((float)q.z, (float)q.w);
        pk[2 * p + 0] = *reinterpret_cast<uint32_t*>(&h0);
        pk[2 * p + 1] = *reinterpret_cast<uint32_t*>(&h1);
    }
    uint4* d4 = reinterpret_cast<uint4*>(dst);
#pragma unroll
    for (int j = 0; j < 4; j++)
        d4[j] = make_uint4(pk[4 * j], pk[4 * j + 1], pk[4 * j + 2], pk[4 * j + 3]);
}

// ---------------- Kernel 3: bf16 HMMA GEMM, ldmatrix frags, fused epilogue ----------------
// CTA 128x128, 8 warps (warp tile 32x64): wm = wid&3, wn = wid>>2.
__global__ void __launch_bounds__(256) gemm_bf_kernel(
    const float* __restrict__ wscale,
    const float* __restrict__ bias,
    float* __restrict__ out
) {
    extern __shared__ char smem[];
    uint32_t sb = smem_to_u32(smem);
    int tid = threadIdx.x, wid = tid >> 5, lane = tid & 31;
    int wm = wid & 3, wn = wid >> 2;
    int g = lane >> 2, tig = lane & 3;

    int n_t = blockIdx.x;
    int m_t = blockIdx.y;

    const char* Ag = reinterpret_cast<const char*>(g_Ab) + ((size_t)(m_t * KITERS) << 14);
    const char* Bg = reinterpret_cast<const char*>(g_Bb) + ((size_t)(n_t * KITERS) << 14);

    // ldmatrix per-lane base offsets (within a stage)
    int quad = lane >> 3, lr = lane & 7;
    uint32_t a_off = (uint32_t)((wm * 32 + (quad & 1) * 8 + lr) * ROWB + (quad >> 1) * 16);
    uint32_t b_off = (uint32_t)(A_STAGE_B + (wn * 64 + (quad >> 1) * 8 + lr) * ROWB + (quad & 1) * 16);

    float acc[2][8][4];
#pragma unroll
    for (int mb = 0; mb < 2; mb++)
#pragma unroll
        for (int nb = 0; nb < 8; nb++)
#pragma unroll
            for (int i = 0; i < 4; i++) acc[mb][nb][i] = 0.0f;

    // prologue: 2 stages
#pragma unroll
    for (int p = 0; p < NSTAGES_B - 1; p++) {
        uint32_t dstA = sb + p * STAGE_B;
        uint32_t dstB = dstA + A_STAGE_B;
        const char* srcA = Ag + ((size_t)p << 14);
        const char* srcB = Bg + ((size_t)p << 14);
#pragma unroll
        for (int j = 0; j < 4; j++) {
            int idx = j * 256 + tid, r = idx >> 3, c = idx & 7;
            CP_ASYNC16(dstA + r * ROWB + c * 16, srcA + idx * 16);
            CP_ASYNC16(dstB + r * ROWB + c * 16, srcB + idx * 16);
        }
        CP_COMMIT();
    }

    for (int kt = 0; kt < KITERS; kt++) {
        CP_WAIT1();
        __syncthreads();
        int kn = kt + NSTAGES_B - 1;
        if (kn < KITERS) {
            int sn = kn % NSTAGES_B;
            uint32_t dstA = sb + sn * STAGE_B;
            uint32_t dstB = dstA + A_STAGE_B;
            const char* srcA = Ag + ((size_t)kn << 14);
            const char* srcB = Bg + ((size_t)kn << 14);
#pragma unroll
            for (int j = 0; j < 4; j++) {
                int idx = j * 256 + tid, r = idx >> 3, c = idx & 7;
                CP_ASYNC16(dstA + r * ROWB + c * 16, srcA + idx * 16);
                CP_ASYNC16(dstB + r * ROWB + c * 16, srcB + idx * 16);
            }
        }
        CP_COMMIT();

        uint32_t stb = sb + (kt % NSTAGES_B) * STAGE_B;
#pragma unroll
        for (int ks = 0; ks < 4; ks++) {           // 4 x k16 per 64-elem stage
            uint32_t ko = (uint32_t)(ks * 32);
            uint32_t a[2][4];
            LDMX4(a[0], stb + a_off + ko);
            LDMX4(a[1], stb + a_off + 16 * ROWB + ko);
#pragma unroll
            for (int nbp = 0; nbp < 4; nbp++) {    // each covers 2 n-blocks
                uint32_t b[4];
                LDMX4(b, stb + b_off + nbp * 16 * ROWB + ko);
                MMA_BF16(acc[0][2 * nbp + 0], a[0], b[0], b[1]);
                MMA_BF16(acc[1][2 * nbp + 0], a[1], b[0], b[1]);
                MMA_BF16(acc[0][2 * nbp + 1], a[0], b[2], b[3]);
                MMA_BF16(acc[1][2 * nbp + 1], a[1], b[2], b[3]);
            }
        }
    }

    // ---- epilogue: dequant + bias ----
    float wsc = wscale[0];
#pragma unroll
    for (int mb = 0; mb < 2; mb++) {
        int r_a = m_t * 128 + wm * 32 + mb * 16 + g;
        int r_b = r_a + 8;
        float sca = 1.0f / (g_s[r_a] * wsc);
        float scb = 1.0f / (g_s[r_b] * wsc);
        float* outa = out + (size_t)r_a * OUT_F;
        float* outb = out + (size_t)r_b * OUT_F;
#pragma unroll
        for (int nb = 0; nb < 8; nb++) {
            int col = n_t * 128 + wn * 64 + nb * 8 + tig * 2;
            float2 bi = *reinterpret_cast<const float2*>(bias + col);
            float2 o;
            o.x = acc[mb][nb][0] * sca + bi.x;
            o.y = acc[mb][nb][1] * sca + bi.y;
            *reinterpret_cast<float2*>(outa + col) = o;
            o.x = acc[mb][nb][2] * scb + bi.x;
            o.y = acc[mb][nb][3] * scb + bi.y;
            *reinterpret_cast<float2*>(outb + col) = o;
        }
    }
}

// ---------------- Launch ----------------
extern "C" void kernel_launch(void* const* d_in, const int* in_sizes, int n_in,
                              void* d_out, int out_size) {
    const float* x      = (const float*)d_in[0];
    const int*   weight = (const int*)d_in[1];
    const float* wscale = (const float*)d_in[2];
    const float* bias   = (const float*)d_in[3];
    float*       out    = (float*)d_out;

    prep_x_kernel<<<TOKENS, 256>>>(x);
    prep_w_kernel<<<OUT_F, 256>>>(weight);

    cudaFuncSetAttribute(gemm_bf_kernel, cudaFuncAttributeMaxDynamicSharedMemorySize, GEMM_SMEM_B);
    gemm_bf_kernel<<<dim3(NTILES, MTILES), 256, GEMM_SMEM_B>>>(wscale, bias, out);
}